// round 16
// baseline (speedup 1.0000x reference)
#include <cuda_runtime.h>
#include <cuda_fp16.h>
#include <stdint.h>

// OptimizerNetwork: 2-layer LSTM-cell meta-optimizer, N=1e6 rows, H=20.
// Lineage: R7 HMMA -> R12/R13 fp16 cuts -> R14 mt-split -> R15 5 CTAs/SM
// (121.3us, 96 regs, DRAM 61%, ~5.3TB/s useful of ~6.3 achievable).
// R16: (1) hoist c-state LDGs above each half-GEMM so their ~600cyc latency
// hides under the 50-MMA block; (2) __ldcs/__stcs streaming hints on all
// read-once/write-once global traffic. Otherwise byte-identical R15.

#define TPB 128
typedef unsigned uns;

// ---- smem layout (bytes) ----
#define A_OFF     0u        // [128][58] fp16; row stride 116B
#define A_STRIDE  116u
#define B1_OFF    14848u    // [80][40] fp16; row stride 80B
#define B1_STRIDE 80u
#define B2_OFF    21248u    // [80][56] fp16; row stride 112B
#define B2_STRIDE 112u
#define WOUT_OFF  30208u    // float[20]
#define BOUT_OFF  30288u    // float
#define SMEM_BYTES 30304u

__device__ __forceinline__ float tanha(float x) {
    float r; asm("tanh.approx.f32 %0, %1;" : "=f"(r) : "f"(x)); return r;
}
__device__ __forceinline__ float sigm(float x) {
    return fmaf(0.5f, tanha(0.5f * x), 0.5f);
}

// store float pair as fp16 (cols col,col+1; col even)
__device__ __forceinline__ void stA2(char* sm, int row, int col, float a, float b) {
    __half2 hv; hv.x = __float2half_rn(a); hv.y = __float2half_rn(b);
    *(__half2*)(sm + A_OFF + row * A_STRIDE + col * 2) = hv;
}
__device__ __forceinline__ void stA1(char* sm, int row, int col, float a) {
    *(__half*)(sm + A_OFF + row * A_STRIDE + col * 2) = __float2half_rn(a);
}
__device__ __forceinline__ void stB(char* sm, uns off, uns stride,
                                    int row, int col, float v) {
    *(__half*)(sm + off + row * stride + col * 2) = __float2half_rn(v);
}

__device__ __forceinline__ void mma16816(float* c, const uns* a, const uns* b) {
    asm volatile("mma.sync.aligned.m16n8k16.row.col.f32.f16.f16.f32 "
        "{%0,%1,%2,%3}, {%4,%5,%6,%7}, {%8,%9}, {%0,%1,%2,%3};"
        : "+f"(c[0]), "+f"(c[1]), "+f"(c[2]), "+f"(c[3])
        : "r"(a[0]), "r"(a[1]), "r"(a[2]), "r"(a[3]), "r"(b[0]), "r"(b[1]));
}

// A fragment: rows mbase+(l/4), +8; k = kb+(l%4)*2, +8
__device__ __forceinline__ void ldA(uns* a, const char* abase, int mbase, int kb, int l) {
    const char* p = abase + (mbase + (l >> 2)) * A_STRIDE + (kb + (l & 3) * 2) * 2;
    a[0] = *(const uns*)p;
    a[1] = *(const uns*)(p + 8 * A_STRIDE);
    a[2] = *(const uns*)(p + 16);
    a[3] = *(const uns*)(p + 8 * A_STRIDE + 16);
}
__device__ __forceinline__ void ldB(uns* b, const char* bbase, uns stride,
                                    int nbase, int kb, int l) {
    const char* p = bbase + (nbase + (l >> 2)) * stride + (kb + (l & 3) * 2) * 2;
    b[0] = *(const uns*)p;
    b[1] = *(const uns*)(p + 16);
}

// half-slab GEMM (16 rows): C[10][4] = A[mrow..mrow+15, :] * B
template <int KS>
__device__ __forceinline__ void gemm_half(float C[10][4], const char* sm,
                                          uns boff, uns bstride, int mrow, int l) {
#pragma unroll
    for (int n = 0; n < 10; ++n)
#pragma unroll
        for (int q = 0; q < 4; ++q) C[n][q] = 0.f;
#pragma unroll
    for (int k = 0; k < KS; ++k) {
        uns a0[4];
        ldA(a0, sm + A_OFF, mrow, k * 16, l);
#pragma unroll
        for (int n = 0; n < 10; ++n) {
            uns b[2];
            ldB(b, sm + boff, bstride, n * 8, k * 16, l);
            mma16816(C[n], a0, b);
        }
    }
}

__global__ void __launch_bounds__(TPB, 5)
optnet_mma(const float* __restrict__ inp,
           const float* __restrict__ h0g, const float* __restrict__ h1g,
           const float* __restrict__ c0g, const float* __restrict__ c1g,
           const float* __restrict__ Wih1, const float* __restrict__ Whh1,
           const float* __restrict__ bih1, const float* __restrict__ bhh1,
           const float* __restrict__ Wih2, const float* __restrict__ Whh2,
           const float* __restrict__ bih2, const float* __restrict__ bhh2,
           const float* __restrict__ Wout, const float* __restrict__ bout,
           float* __restrict__ out, int N)
{
    extern __shared__ char sm[];
    const int tid = threadIdx.x;
    const int wid = tid >> 5;
    const int l = tid & 31;

    // ---- prologue: zero, stage gate-permuted fp16 weights + consts ----
    for (int i = tid; i < (int)(SMEM_BYTES / 16); i += TPB)
        ((float4*)sm)[i] = make_float4(0.f, 0.f, 0.f, 0.f);
    __syncthreads();

    // B row p: p=2h -> i_h (W row h), 2h+1 -> f_h (20+h),
    //          40+2h -> g_h (40+h), 41+2h -> o_h (60+h)
    if (tid < 80) {
        const int p = tid;
        int h, r;
        if (p < 40) { h = p >> 1; r = (p & 1) ? 20 + h : h; }
        else { int q = p - 40; h = q >> 1; r = (q & 1) ? 60 + h : 40 + h; }
        stB(sm, B1_OFF, B1_STRIDE, p, 0, Wih1[r * 2 + 0]);
        stB(sm, B1_OFF, B1_STRIDE, p, 1, Wih1[r * 2 + 1]);
        for (int k = 0; k < 20; ++k) {
            stB(sm, B1_OFF, B1_STRIDE, p, 2 + k, Whh1[r * 20 + k]);
            stB(sm, B2_OFF, B2_STRIDE, p, k, Wih2[r * 20 + k]);
            stB(sm, B2_OFF, B2_STRIDE, p, 20 + k, Whh2[r * 20 + k]);
        }
        stB(sm, B1_OFF, B1_STRIDE, p, 22, bih1[r] + bhh1[r]);
        stB(sm, B2_OFF, B2_STRIDE, p, 40, bih2[r] + bhh2[r]);
    }
    if (tid < 20) ((float*)(sm + WOUT_OFF))[tid] = Wout[tid];
    if (tid == 0) *(float*)(sm + BOUT_OFF) = bout[0];
    // A bias col 40 (cell2) set once; never overwritten per-slab.
    stA2(sm, (wid << 5) | l, 40, 1.f, 0.f);
    __syncthreads();

    float woutR[5];
#pragma unroll
    for (int j = 0; j < 5; ++j)
        woutR[j] = ((const float*)(sm + WOUT_OFF))[(l & 3) + 4 * j];
    const float boutv = *(const float*)(sm + BOUT_OFF);

    // output tuple sections: out, h0n@N, h1n@21N, c0n@41N, c1n@61N
    float* h0n_out = out + (size_t)N;
    float* h1n_out = out + (size_t)N * 21;
    float* c0n_out = out + (size_t)N * 41;
    float* c1n_out = out + (size_t)N * 61;

    const int wrow = wid * 32;
    const int nslabs = (N + 31) / 32;
    const int twarps = gridDim.x * 4;
    float C[10][4];

    for (int s = blockIdx.x * 4 + wid; s < nslabs; s += twarps) {
        const int rowbase = s * 32;

        // ---- stage A cell1: x_pre (0,1), bias (22), h0 (2..21) ----
        {
            const int grow = rowbase + l;
            float x = (grow < N) ? __ldcs(inp + grow) : 0.f;
            float ax = fabsf(x), pa, pb;
            if (ax >= 4.5399930e-05f) {        // exp(-10)
                pa = __logf(ax + 1e-8f) * 0.1f;
                pb = (x > 0.f) ? 1.f : -1.f;
            } else {
                pa = -1.f;
                pb = 22026.4658f * x;          // exp(10)
            }
            stA2(sm, wrow + l, 0, pa, pb);
            stA2(sm, wrow + l, 22, 1.f, 0.f);  // clobbered by h1 staging later
#pragma unroll
            for (int q = 0; q < 5; ++q) {
                const int idx = q * 32 + l;
                const int gr = idx / 5, cp = idx % 5;
                float4 v = make_float4(0.f, 0.f, 0.f, 0.f);
                if (rowbase + gr < N)
                    v = __ldcs(((const float4*)(h0g + (size_t)rowbase * 20)) + idx);
                stA2(sm, wrow + gr, 2 + cp * 4, v.x, v.y);
                stA2(sm, wrow + gr, 4 + cp * 4, v.z, v.w);
            }
        }
        __syncwarp();

        // ---- cell1: two 16-row halves; c0 loads hoisted above the GEMM ----
#pragma unroll
        for (int mt = 0; mt < 2; ++mt) {
            float cin[2][5];
#pragma unroll
            for (int r = 0; r < 2; ++r) {
                const int rloc = (l >> 2) + 16 * mt + 8 * r;
                const size_t grow = (size_t)rowbase + rloc;
                const bool ok = grow < (size_t)N;
#pragma unroll
                for (int j = 0; j < 5; ++j) {
                    const int h = (l & 3) + 4 * j;
                    cin[r][j] = ok ? __ldcs(c0g + grow * 20 + h) : 0.f;
                }
            }
            gemm_half<2>(C, sm, B1_OFF, B1_STRIDE, wrow + 16 * mt, l);
            __syncwarp();
#pragma unroll
            for (int r = 0; r < 2; ++r) {                 // cb = 2r
                const int cb = r * 2;
                const int rloc = (l >> 2) + 16 * mt + 8 * r;
                const size_t grow = (size_t)rowbase + rloc;
                const bool ok = grow < (size_t)N;
#pragma unroll
                for (int j = 0; j < 5; ++j) {
                    const int h = (l & 3) + 4 * j;
                    float I = sigm(C[j][cb]);
                    float F = sigm(C[j][cb + 1]);
                    float G = tanha(C[j + 5][cb]);
                    float O = sigm(C[j + 5][cb + 1]);
                    float cn = fmaf(F, cin[r][j], I * G);
                    float hn = O * tanha(cn);
                    if (ok) {
                        __stcs(c0n_out + grow * 20 + h, cn);
                        __stcs(h0n_out + grow * 20 + h, hn);
                    }
                    stA1(sm, wrow + rloc, h, hn);         // cell2 A cols 0..19
                }
            }
            __syncwarp();
        }

        // ---- stage h1 (cols 20..39); bias col 40 persists ----
#pragma unroll
        for (int q = 0; q < 5; ++q) {
            const int idx = q * 32 + l;
            const int gr = idx / 5, cp = idx % 5;
            float4 v = make_float4(0.f, 0.f, 0.f, 0.f);
            if (rowbase + gr < N)
                v = __ldcs(((const float4*)(h1g + (size_t)rowbase * 20)) + idx);
            stA2(sm, wrow + gr, 20 + cp * 4, v.x, v.y);
            stA2(sm, wrow + gr, 22 + cp * 4, v.z, v.w);
        }
        __syncwarp();

        // ---- cell2: two 16-row halves; c1 loads hoisted; fold output dot ----
#pragma unroll
        for (int mt = 0; mt < 2; ++mt) {
            float cin[2][5];
#pragma unroll
            for (int r = 0; r < 2; ++r) {
                const int rloc = (l >> 2) + 16 * mt + 8 * r;
                const size_t grow = (size_t)rowbase + rloc;
                const bool ok = grow < (size_t)N;
#pragma unroll
                for (int j = 0; j < 5; ++j) {
                    const int h = (l & 3) + 4 * j;
                    cin[r][j] = ok ? __ldcs(c1g + grow * 20 + h) : 0.f;
                }
            }
            gemm_half<3>(C, sm, B2_OFF, B2_STRIDE, wrow + 16 * mt, l);
            __syncwarp();
#pragma unroll
            for (int r = 0; r < 2; ++r) {
                const int cb = r * 2;
                const int rloc = (l >> 2) + 16 * mt + 8 * r;
                const size_t grow = (size_t)rowbase + rloc;
                const bool ok = grow < (size_t)N;
                float psum = 0.f;
#pragma unroll
                for (int j = 0; j < 5; ++j) {
                    const int h = (l & 3) + 4 * j;
                    float I = sigm(C[j][cb]);
                    float F = sigm(C[j][cb + 1]);
                    float G = tanha(C[j + 5][cb]);
                    float O = sigm(C[j + 5][cb + 1]);
                    float cn = fmaf(F, cin[r][j], I * G);
                    float hn = O * tanha(cn);
                    if (ok) {
                        __stcs(c1n_out + grow * 20 + h, cn);
                        __stcs(h1n_out + grow * 20 + h, hn);
                    }
                    psum = fmaf(hn, woutR[j], psum);
                }
                psum += __shfl_xor_sync(0xFFFFFFFFu, psum, 1);
                psum += __shfl_xor_sync(0xFFFFFFFFu, psum, 2);
                if (ok && (l & 3) == 0) __stcs(out + grow, psum + boutv);
            }
            __syncwarp();
        }
    }
}

extern "C" void kernel_launch(void* const* d_in, const int* in_sizes, int n_in,
                              void* d_out, int out_size)
{
    static int configured = 0;
    if (!configured) {
        cudaFuncSetAttribute(optnet_mma,
                             cudaFuncAttributeMaxDynamicSharedMemorySize,
                             SMEM_BYTES);
        configured = 1;
    }
    const int N = in_sizes[0];
    const int grid = 740;   // 5 CTAs/SM x 148 SMs, persistent
    optnet_mma<<<grid, TPB, SMEM_BYTES>>>(
        (const float*)d_in[0], (const float*)d_in[1], (const float*)d_in[2],
        (const float*)d_in[3], (const float*)d_in[4],
        (const float*)d_in[5], (const float*)d_in[6],
        (const float*)d_in[7], (const float*)d_in[8],
        (const float*)d_in[9], (const float*)d_in[10],
        (const float*)d_in[11], (const float*)d_in[12],
        (const float*)d_in[13], (const float*)d_in[14],
        (float*)d_out, N);
}